// round 6
// baseline (speedup 1.0000x reference)
#include <cuda_runtime.h>
#include <math.h>

#define NB 16
#define TT 12
#define AL 0.2f

// Dynamic smem (floats): s_W[4096] | s_src[8192]
#define DYN_BYTES ((4096 + 8192) * 4)

__global__ __launch_bounds__(512) void gat_one(
    const float* __restrict__ inp,   // [NB,TT,64,64]
    const float* __restrict__ W,     // [64,64]
    const float* __restrict__ a,     // [128]
    float* __restrict__ out_elu,     // [NB,TT,64,64]
    float* __restrict__ out_att,     // [NB,TT,64,64]
    int write_att)
{
    extern __shared__ float sm[];
    float* s_W   = sm;            // 64x64
    float* s_src = sm + 4096;     // double source slab: 128x64

    __shared__ __align__(16) float s_a [128];
    __shared__ __align__(16) float s_WA[128];   // ti<6: WA1[64]; ti>=6: WAlo|WAhi
    __shared__ __align__(16) float s_cs[128];   // ti<6 own half colsums
    __shared__ __align__(16) float s_g [256];   // ti<6: g1[128]; ti>=6: g2a[128]|g2b[128]
    __shared__ __align__(16) float s_SW[128];   // ti<6: SW_lo|SW_hi
    __shared__ __align__(16) float s_p0[64], s_p1[64];   // ti<6 probs per row v
    __shared__ __align__(16) float s_att[64];   // ti>=6: att[vb*32+w']
    __shared__ __align__(16) float s_wc[128], s_q[128];

    const int t    = threadIdx.x;
    const int pair = blockIdx.x;                // n*TT + ti
    const int n = pair / TT, ti = pair - n * TT;
    const bool first = (ti < 6);
    const int ts = first ? 2 * ti : 2 * (ti - 6);
    const float* src = inp + (size_t)(n * TT + ts) * 4096;  // 2 consecutive slabs
    const float* own = inp + (size_t)pair * 4096;

    // ---- Stage A: stage W + src double-slab; ti<6 colsums direct from global ----
    {
        const float4* Wg = (const float4*)W;
        const float4* Sg = (const float4*)src;
        float4* Ws = (float4*)s_W;
        float4* Ss = (float4*)s_src;
#pragma unroll
        for (int i = 0; i < 2; i++) Ws[t + i * 512] = Wg[t + i * 512];
#pragma unroll
        for (int i = 0; i < 4; i++) Ss[t + i * 512] = Sg[t + i * 512];
        if (t < 128) s_a[t] = a[t];
        if (first && t >= 256) {
            const int d = (t - 256) >> 1, p = t & 1;
            const int hb = d >> 6, k = d & 63;
            const float* op = own + (hb * 32 + p * 16) * 64 + k;
            float s0 = 0.f, s1 = 0.f;
#pragma unroll
            for (int w = 0; w < 16; w += 2) { s0 += op[w * 64]; s1 += op[(w + 1) * 64]; }
            float s = s0 + s1;
            s += __shfl_xor_sync(0xffffffffu, s, 1);
            if (!p) s_cs[d] = s;                 // sum over 32 rows of half hb, col k
        }
    }
    __syncthreads();

    // ---- Stage B: WA matvec(s); ti<6 also SW matvecs ----
    if (first) {
        if (t < 128) {                           // WA1[k], 2 threads per k
            const int k = t >> 1, p = t & 1;
            float s0 = 0.f, s1 = 0.f;
#pragma unroll
            for (int i = 0; i < 32; i += 2) {
                const int ja = (2 * i + p + 2 * k) & 63;
                const int jb = (2 * (i + 1) + p + 2 * k) & 63;
                s0 = fmaf(s_W[k * 64 + ja], s_a[ja] + s_a[64 + ja], s0);
                s1 = fmaf(s_W[k * 64 + jb], s_a[jb] + s_a[64 + jb], s1);
            }
            float s = s0 + s1;
            s += __shfl_xor_sync(0xffffffffu, s, 1);
            if (!p) s_WA[k] = s;
        } else if (t < 384) {                    // SW_c[j] = cs_c . W[:,j]
            const int d = (t - 128) >> 1, p = t & 1;
            const int c = d >> 6, j = d & 63;
            const float* cs = s_cs + c * 64;
            float s0 = 0.f, s1 = 0.f;
#pragma unroll
            for (int i = 0; i < 32; i += 2) {
                const int ka = p * 32 + i, kb = ka + 1;
                s0 = fmaf(cs[ka], s_W[ka * 64 + j], s0);
                s1 = fmaf(cs[kb], s_W[kb * 64 + j], s1);
            }
            float s = s0 + s1;
            s += __shfl_xor_sync(0xffffffffu, s, 1);
            if (!p) s_SW[c * 64 + j] = s;
        }
    } else {
        if (t < 256) {                           // WA_c[k]
            const int d = t >> 1, p = t & 1;
            const int c = d >> 6, k = d & 63;
            const float* av = s_a + c * 64;
            float s0 = 0.f, s1 = 0.f;
#pragma unroll
            for (int i = 0; i < 32; i += 2) {
                const int ja = (2 * i + p + 2 * k) & 63;
                const int jb = (2 * (i + 1) + p + 2 * k) & 63;
                s0 = fmaf(s_W[k * 64 + ja], av[ja], s0);
                s1 = fmaf(s_W[k * 64 + jb], av[jb], s1);
            }
            float s = s0 + s1;
            s += __shfl_xor_sync(0xffffffffu, s, 1);
            if (!p) s_WA[c * 64 + k] = s;
        }
    }
    __syncthreads();

    // ---- Stage C: g dots over the 128 src rows ----
    if (first) {
        if (t < 256) {                           // g1[u]
            const int u = t >> 1, p = t & 1;
            float s0 = 0.f, s1 = 0.f;
#pragma unroll
            for (int i = 0; i < 32; i += 2) {
                const int ka = (2 * i + p + 2 * u) & 63;
                const int kb = (2 * (i + 1) + p + 2 * u) & 63;
                s0 = fmaf(s_src[u * 64 + ka], s_WA[ka], s0);
                s1 = fmaf(s_src[u * 64 + kb], s_WA[kb], s1);
            }
            float s = s0 + s1;
            s += __shfl_xor_sync(0xffffffffu, s, 1);
            if (!p) s_g[u] = s;
        }
    } else {                                     // g2a (d<128) | g2b (d>=128)
        const int d = t >> 1, p = t & 1;
        const int c = d >> 7, u = d & 127;
        const float* wav = s_WA + c * 64;
        float s0 = 0.f, s1 = 0.f;
#pragma unroll
        for (int i = 0; i < 32; i += 2) {
            const int ka = (2 * i + p + 2 * u) & 63;
            const int kb = (2 * (i + 1) + p + 2 * u) & 63;
            s0 = fmaf(s_src[u * 64 + ka], wav[ka], s0);
            s1 = fmaf(s_src[u * 64 + kb], wav[kb], s1);
        }
        float s = s0 + s1;
        s += __shfl_xor_sync(0xffffffffu, s, 1);
        if (!p) s_g[d] = s;
    }
    __syncthreads();

    // ---- Stage D: softmax ----
    if (first) {
        if (t < 64) {
            const int v = t, vb = v >> 5;
            float e0 = s_g[vb * 64 + 2 * (v & 31)];
            float e1 = s_g[vb * 64 + 2 * (v & 31) + 1];
            e0 = (e0 > 0.f) ? e0 : AL * e0;
            e1 = (e1 > 0.f) ? e1 : AL * e1;
            const float m = fmaxf(e0, e1);
            const float p0 = __expf(e0 - m), p1 = __expf(e1 - m);
            const float inv = 1.f / (32.f * (p0 + p1));
            s_p0[v] = p0 * inv;
            s_p1[v] = p1 * inv;
        }
        __syncthreads();

        // ---- Stage E: outputs (64 rows x 64 cols) ----
        float4* oe4 = (float4*)(out_elu + (size_t)pair * 4096);
        float4* oa4 = (float4*)(out_att + (size_t)pair * 4096);
        const float4* Qlo = (const float4*)s_SW;
        const float4* Qhi = (const float4*)(s_SW + 64);
#pragma unroll
        for (int i = 0; i < 2; i++) {
            const int idx4 = t + i * 512;        // [0,1024)
            const int v = idx4 >> 4, w4 = idx4 & 15;
            const float a0 = s_p0[v], a1 = s_p1[v];
            const float4 q0 = Qlo[w4], q1 = Qhi[w4];
            float4 r;
            r.x = fmaf(a0, q0.x, a1 * q1.x);
            r.y = fmaf(a0, q0.y, a1 * q1.y);
            r.z = fmaf(a0, q0.z, a1 * q1.z);
            r.w = fmaf(a0, q0.w, a1 * q1.w);
            r.x = (r.x > 0.f) ? r.x : (__expf(r.x) - 1.f);
            r.y = (r.y > 0.f) ? r.y : (__expf(r.y) - 1.f);
            r.z = (r.z > 0.f) ? r.z : (__expf(r.z) - 1.f);
            r.w = (r.w > 0.f) ? r.w : (__expf(r.w) - 1.f);
            oe4[idx4] = r;
            if (write_att) {
                const float av = (w4 < 8) ? a0 : a1;
                oa4[idx4] = make_float4(av, av, av, av);
            }
        }
    } else {
        if (t < 64) {                            // warp 0: vb=0, warp 1: vb=1
            const int vb = t >> 5, ln = t & 31;
            float e = s_g[vb * 64 + 2 * ln] + s_g[128 + vb * 64 + 2 * ln + 1];
            e = (e > 0.f) ? e : AL * e;
            float m = e;
#pragma unroll
            for (int o = 16; o; o >>= 1) m = fmaxf(m, __shfl_xor_sync(0xffffffffu, m, o));
            const float p = __expf(e - m);
            float ss = p;
#pragma unroll
            for (int o = 16; o; o >>= 1) ss += __shfl_xor_sync(0xffffffffu, ss, o);
            s_att[t] = p / (2.f * ss);
        }
        __syncthreads();

        // ---- Stage E: weighted colsums of own slab (direct from global) ----
        if (t < 256) {
            const int d = t >> 1, p = t & 1;
            const int vb = d >> 6, k = d & 63;
            float s0 = 0.f, s1 = 0.f;
#pragma unroll
            for (int i = 0; i < 16; i += 2) {
                const int w = p * 16 + i;
                s0 = fmaf(s_att[vb * 32 + w],
                          own[w * 64 + k] + own[(w + 32) * 64 + k], s0);
                s1 = fmaf(s_att[vb * 32 + w + 1],
                          own[(w + 1) * 64 + k] + own[(w + 33) * 64 + k], s1);
            }
            float s = s0 + s1;
            s += __shfl_xor_sync(0xffffffffu, s, 1);
            if (!p) s_wc[vb * 64 + k] = s;
        }
        __syncthreads();

        // ---- Stage F: q[vb][j] = wc[vb] . W[:,j], fold ELU ----
        if (t < 256) {
            const int d = t >> 1, p = t & 1;
            const int vb = d >> 6, j = d & 63;
            const float* wv = s_wc + vb * 64;
            float s0 = 0.f, s1 = 0.f;
#pragma unroll
            for (int i = 0; i < 32; i += 2) {
                const int ka = p * 32 + i, kb = ka + 1;
                s0 = fmaf(wv[ka], s_W[ka * 64 + j], s0);
                s1 = fmaf(wv[kb], s_W[kb * 64 + j], s1);
            }
            float s = s0 + s1;
            s += __shfl_xor_sync(0xffffffffu, s, 1);
            if (!p) {
                const float q = s;
                s_q[vb * 64 + j] = (q > 0.f) ? q : (__expf(q) - 1.f);
            }
        }
        __syncthreads();

        // ---- Stage G: broadcast outputs ----
        float4* oe4 = (float4*)(out_elu + (size_t)pair * 4096);
        float4* oa4 = (float4*)(out_att + (size_t)pair * 4096);
        const float4* Q4 = (const float4*)s_q;
        const float4* A4 = (const float4*)s_att;
#pragma unroll
        for (int i = 0; i < 2; i++) {
            const int idx4 = t + i * 512;
            const int v = idx4 >> 4, vb = v >> 5, w4 = idx4 & 15;
            oe4[idx4] = Q4[vb * 16 + w4];
            if (write_att) oa4[idx4] = A4[vb * 8 + (w4 & 7)];
        }
    }
}

extern "C" void kernel_launch(void* const* d_in, const int* in_sizes, int n_in,
                              void* d_out, int out_size)
{
    const float* inp = (const float*)d_in[0];   // [16,12,64,64]
    // d_in[1] = adj — dead in the reference
    const float* W   = (const float*)d_in[2];   // [64,64]
    const float* a   = (const float*)d_in[3];   // [128,1]
    float* out = (float*)d_out;

    const int elu_elems = NB * TT * 64 * 64;    // 786432
    const int write_att = (out_size >= 2 * elu_elems) ? 1 : 0;
    float* out_att = out + elu_elems;

    static int smem_set = 0;
    if (!smem_set) {
        cudaFuncSetAttribute(gat_one, cudaFuncAttributeMaxDynamicSharedMemorySize,
                             DYN_BYTES);
        smem_set = 1;
    }
    gat_one<<<NB * TT, 512, DYN_BYTES>>>(inp, W, a, out, out_att, write_att);
}